// round 15
// baseline (speedup 1.0000x reference)
#include <cuda_runtime.h>
#include <cuda_bf16.h>
#include <cstdint>

#define BB 2
#define CIN 128
#define COUT 64
#define KK 64
#define HWD 16384          // 128*128
#define NPIX (BB*HWD)      // 32768
#define GPX 64             // pixels per gemm block
#define NGB (NPIX/GPX)     // 512 gemm blocks

// ---------------- scratch (device globals; no allocation) ----------------
__device__ float g_xt[BB*COUT*HWD];        // xt in [b][o][p] layout (8MB)
__device__ float g_sumsp[BB*KK*COUT*2];    // partial bin sums [b][k][o][z]
__device__ float g_cntp[BB*KK*2];          // partial counts   [b][k][z]
__device__ float g_L[COUT*COUT];           // Cholesky factor L (lower) of cov
__device__ float g_rd[COUT];               // 1/L[i][i]
__device__ float g_Z[BB*KK*COUT];          // z_k = L^-1 m_k, [b][k][o]
__device__ float g_adjmT[BB*KK*COUT];      // adj @ means, TRANSPOSED [b][o][i]
__device__ float g_psum[16*COUT];          // BN partial sums  [(b*8+cx)][o]
__device__ float g_psq[16*COUT];           // BN partial sumsq

// macro params named to avoid .x/.y/.z/.w member-token capture
#define FMA4(ACC_, XS_, WV_) { (ACC_).x += (XS_)*(WV_).x; (ACC_).y += (XS_)*(WV_).y; (ACC_).z += (XS_)*(WV_).z; (ACC_).w += (XS_)*(WV_).w; }

// ---------------- GEMM xt = x*Wft (block>0) + register-resident Cholesky (block 0) ----------------
__global__ void __launch_bounds__(256) k_gemm(const float* __restrict__ x,
                                              const float* __restrict__ Wft,
                                              const float* __restrict__ Wm) {
    __shared__ __align__(16) float sbuf[8192];   // gemm: W float4[2048]; chol: cov 64*65 then colbuf/dbuf
    const int tid = threadIdx.x;

    if (blockIdx.x == 0) {
        // ======== cov = Wm Wm^T, then Cholesky with matrix in registers ========
        for (int i = tid; i < 64*64; i += 256) sbuf[(i >> 6)*65 + (i & 63)] = Wm[i];
        __syncthreads();
        // cov via 4x4 register tile (16x16 thread grid)
        const int ti = tid & 15;
        const int tj = tid >> 4;
        float acc[4][4];
        #pragma unroll
        for (int p = 0; p < 4; p++)
            #pragma unroll
            for (int q = 0; q < 4; q++) acc[p][q] = 0.f;
        for (int c = 0; c < 64; c++) {
            float ai[4], bj[4];
            #pragma unroll
            for (int p = 0; p < 4; p++) ai[p] = sbuf[(ti*4 + p)*65 + c];
            #pragma unroll
            for (int q = 0; q < 4; q++) bj[q] = sbuf[(tj*4 + q)*65 + c];
            #pragma unroll
            for (int p = 0; p < 4; p++)
                #pragma unroll
                for (int q = 0; q < 4; q++) acc[p][q] += ai[p] * bj[q];
        }
        __syncthreads();
        #pragma unroll
        for (int p = 0; p < 4; p++)
            #pragma unroll
            for (int q = 0; q < 4; q++) sbuf[(ti*4 + p)*65 + tj*4 + q] = acc[p][q];
        __syncthreads();

        // load 16 cells per thread into registers: row r, cols j0..j0+15
        const int r = tid & 63;
        const int part = tid >> 6;
        const int j0 = part*16;
        float creg[16];
        #pragma unroll
        for (int jj = 0; jj < 16; jj++) creg[jj] = sbuf[r*65 + j0 + jj];
        __syncthreads();   // all cov reads done; sbuf[0..64] now colbuf/dbuf

        // Cholesky: 64 steps, <=1 STS per thread per barrier (cheap drain)
        #pragma unroll
        for (int i = 0; i < 64; i++) {
            if (r == i && part == (i >> 4)) sbuf[64] = creg[i & 15];   // dbuf = C[i][i]
            __syncthreads();
            if (part == (i >> 4) && r >= i) {
                float rpiv = rsqrtf(sbuf[64]);
                float Lv = creg[i & 15] * rpiv;
                creg[i & 15] = Lv;
                sbuf[r] = Lv;                  // colbuf[r] = L[r][i]
                if (r == i) g_rd[i] = rpiv;    // 1/L[i][i]
            }
            __syncthreads();
            if (r > i) {
                float f = sbuf[r];             // L[r][i]
                #pragma unroll
                for (int jj = 0; jj < 16; jj++) {
                    int j = j0 + jj;
                    if (j > i && j <= r) creg[jj] -= f * sbuf[j];
                }
            }
        }
        // write L (lower incl diag; upper zeros)
        #pragma unroll
        for (int jj = 0; jj < 16; jj++) {
            int j = j0 + jj;
            g_L[r*64 + j] = (j <= r) ? creg[jj] : 0.f;
        }
        return;
    }

    // ======== GEMM: 64 px x 64 outs; 256 thr; thread tile 4px x 4out; register-pipelined LDG ========
    float4* sW4 = reinterpret_cast<float4*>(sbuf);          // [128c][16 f4]
    const int GP = (blockIdx.x - 1) * GPX;
    const int b  = GP >> 14;
    const int P0 = GP & (HWD - 1);
    const int quad = tid & 15;        // pixel quad: px = quad*4..+3
    const int og   = tid >> 4;        // out group: o = og*4..+3

    #pragma unroll
    for (int t = 0; t < 8; t++)
        sW4[tid + t*256] = __ldg(reinterpret_cast<const float4*>(Wft) + tid + t*256);
    __syncthreads();

    float4 a0 = make_float4(0.f,0.f,0.f,0.f), a1 = a0, a2 = a0, a3 = a0;

    const float* xb = x + (size_t)b * CIN * HWD + P0 + quad*4;
    const float4* sWp = sW4 + og;

    float4 L[4];
    #pragma unroll
    for (int i = 0; i < 4; i++)
        L[i] = *reinterpret_cast<const float4*>(xb + (size_t)i * HWD);

    for (int cb = 0; cb < CIN; cb += 4) {
        float4 M[4];
        if (cb + 4 < CIN) {
            #pragma unroll
            for (int i = 0; i < 4; i++)
                M[i] = *reinterpret_cast<const float4*>(xb + (size_t)(cb + 4 + i) * HWD);
        }
        #pragma unroll
        for (int i = 0; i < 4; i++) {
            float4 wv = sWp[(cb + i)*16];
            FMA4(a0, L[i].x, wv);
            FMA4(a1, L[i].y, wv);
            FMA4(a2, L[i].z, wv);
            FMA4(a3, L[i].w, wv);
        }
        #pragma unroll
        for (int i = 0; i < 4; i++) L[i] = M[i];
    }

    float* xtb = g_xt + (size_t)b * COUT * HWD + P0 + quad*4;
    const int ob = og*4;
    *reinterpret_cast<float4*>(xtb + (size_t)(ob+0) * HWD) = make_float4(a0.x, a1.x, a2.x, a3.x);
    *reinterpret_cast<float4*>(xtb + (size_t)(ob+1) * HWD) = make_float4(a0.y, a1.y, a2.y, a3.y);
    *reinterpret_cast<float4*>(xtb + (size_t)(ob+2) * HWD) = make_float4(a0.z, a1.z, a2.z, a3.z);
    *reinterpret_cast<float4*>(xtb + (size_t)(ob+3) * HWD) = make_float4(a0.w, a1.w, a2.w, a3.w);
}

// ---------------- kernel: per-bin partial sums + counts via shared atomics ----------------
__global__ void __launch_bounds__(256) k_sums(const int* __restrict__ idx) {
    __shared__ float sbm[64*33];
    const int tid = threadIdx.x;
    const int o = blockIdx.x, b = blockIdx.y, z = blockIdx.z;
    for (int i = tid; i < 64*33; i += 256) sbm[i] = 0.f;
    __syncthreads();
    const int col = tid & 31;
    const int4* ip4 = reinterpret_cast<const int4*>(idx + b*HWD);
    const int q0 = z*2048;
    if (o < COUT) {
        const float4* xt4 = reinterpret_cast<const float4*>(g_xt + (size_t)(b*COUT + o) * HWD);
        #pragma unroll
        for (int it = 0; it < 8; it++) {
            int q = q0 + it*256 + tid;
            float4 v = __ldg(xt4 + q);
            int4 kk = __ldg(ip4 + q);
            atomicAdd(&sbm[kk.x*33 + col], v.x);
            atomicAdd(&sbm[kk.y*33 + col], v.y);
            atomicAdd(&sbm[kk.z*33 + col], v.z);
            atomicAdd(&sbm[kk.w*33 + col], v.w);
        }
    } else {
        #pragma unroll
        for (int it = 0; it < 8; it++) {
            int q = q0 + it*256 + tid;
            int4 kk = __ldg(ip4 + q);
            atomicAdd(&sbm[kk.x*33 + col], 1.f);
            atomicAdd(&sbm[kk.y*33 + col], 1.f);
            atomicAdd(&sbm[kk.z*33 + col], 1.f);
            atomicAdd(&sbm[kk.w*33 + col], 1.f);
        }
    }
    __syncthreads();
    if (tid < 128) {
        int k = tid >> 1, h = tid & 1;
        float s = 0.f;
        const float* row = sbm + k*33 + h*16;
        #pragma unroll
        for (int m = 0; m < 16; m++) s += row[m];
        s += __shfl_xor_sync(0xffffffffu, s, 1);
        if (h == 0) {
            if (o < COUT) g_sumsp[((b*64 + k)*64 + o)*2 + z] = s;
            else          g_cntp[(b*64 + k)*2 + z] = s;
        }
    }
}

// ---------------- kernel: forward solve z_k = L^-1 m_k (per (b,k), no barriers in solve) ----------------
__global__ void __launch_bounds__(64) k_solve() {
    __shared__ float sL[64*64];
    __shared__ float srd[64];
    const int tid = threadIdx.x;
    const int b = blockIdx.x;
    for (int t = tid; t < 64*64; t += 64) sL[t] = g_L[t];
    srd[tid] = g_rd[tid];
    __syncthreads();

    const int k = tid;
    float cnt = g_cntp[(b*64 + k)*2] + g_cntp[(b*64 + k)*2 + 1];
    float den = cnt + (cnt == 0.f ? 1.f : 0.f);
    float m[64];
    #pragma unroll 8
    for (int o = 0; o < 64; o++) {
        float2 sp = *reinterpret_cast<const float2*>(g_sumsp + ((size_t)(b*64 + k)*64 + o)*2);
        m[o] = (sp.x + sp.y) / den;
    }
    float z[64];
    #pragma unroll
    for (int i = 0; i < 64; i++) {
        float a = m[i];
        #pragma unroll
        for (int j = 0; j < i; j++) a -= sL[i*64 + j] * z[j];
        z[i] = a * srd[i];
    }
    float* zp = g_Z + (size_t)(b*64 + k)*64;
    #pragma unroll 8
    for (int o = 0; o < 64; o++) zp[o] = z[o];
}

// ---------------- kernel: adjacency (via ||z_i - z_j||^2) + adj@means per (b,i) ----------------
__global__ void __launch_bounds__(256) k_adj() {
    __shared__ float sMe[64*65];
    __shared__ float sZ[64*65];
    __shared__ float adjrow[64];
    __shared__ float red[256];
    const int tid = threadIdx.x;
    const int b = blockIdx.x >> 6;
    const int i = blockIdx.x & 63;

    for (int t = tid; t < 64*64; t += 256) {
        int k = t >> 6, o = t & 63;
        float2 sp = *reinterpret_cast<const float2*>(g_sumsp + ((size_t)b*4096 + t)*2);
        float sum = sp.x + sp.y;
        float2 cp = *reinterpret_cast<const float2*>(g_cntp + (b*64 + k)*2);
        float cnt = cp.x + cp.y;
        float den = cnt + (cnt == 0.f ? 1.f : 0.f);
        sMe[k*65 + o] = sum / den;
        sZ[k*65 + o] = g_Z[b*4096 + t];
    }
    __syncthreads();

    const int j = tid & 63, s = tid >> 6;
    const float* zi = sZ + i*65;
    const float* zj = sZ + j*65;
    float q = 0.f;
    #pragma unroll
    for (int d = 0; d < 16; d++) {
        float df = zi[s*16 + d] - zj[s*16 + d];
        q += df * df;
    }
    red[tid] = q;
    __syncthreads();
    if (tid < 64) {
        float qt = red[tid] + red[64 + tid] + red[128 + tid] + red[192 + tid];
        float dist = (tid == i) ? 1e-6f : sqrtf(fmaxf(qt, 1e-12f));
        adjrow[tid] = expf(-dist);
    }
    __syncthreads();
    const int o = tid & 63;
    float part = 0.f;
    for (int jj = s*16; jj < s*16 + 16; jj++) part += adjrow[jj] * sMe[jj*65 + o];
    red[tid] = part;
    __syncthreads();
    if (tid < 64)
        g_adjmT[b*4096 + tid*64 + i] = red[tid] + red[64 + tid] + red[128 + tid] + red[192 + tid];
}

// ---------------- kernel: BN partial statistics ----------------
__global__ void __launch_bounds__(256) k_stats(const int* __restrict__ idx) {
    __shared__ float sAm[64];
    const int tid = threadIdx.x;
    const int cx = blockIdx.x, o = blockIdx.y, b = blockIdx.z;
    if (tid < 64) sAm[tid] = g_adjmT[b*4096 + o*64 + tid];
    __syncthreads();
    const float4* xt4 = reinterpret_cast<const float4*>(g_xt + (size_t)(b*COUT + o) * HWD);
    const int4*   ip4 = reinterpret_cast<const int4*>(idx + b*HWD);
    int q0 = cx * 512 + tid;
    float s = 0.f, sq = 0.f;
    #pragma unroll
    for (int it = 0; it < 2; it++) {
        int q = q0 + it*256;
        float4 v = __ldg(xt4 + q);
        int4 kk = __ldg(ip4 + q);
        float f0 = fmaxf(v.x + sAm[kk.x], 0.f);
        float f1 = fmaxf(v.y + sAm[kk.y], 0.f);
        float f2 = fmaxf(v.z + sAm[kk.z], 0.f);
        float f3 = fmaxf(v.w + sAm[kk.w], 0.f);
        s  += f0 + f1 + f2 + f3;
        sq += f0*f0 + f1*f1 + f2*f2 + f3*f3;
    }
    #pragma unroll
    for (int off = 16; off; off >>= 1) {
        s  += __shfl_down_sync(0xffffffffu, s, off);
        sq += __shfl_down_sync(0xffffffffu, sq, off);
    }
    __shared__ float rs[8], rq[8];
    if ((tid & 31) == 0) { rs[tid >> 5] = s; rq[tid >> 5] = sq; }
    __syncthreads();
    if (tid == 0) {
        float S = 0.f, Q = 0.f;
        #pragma unroll
        for (int w = 0; w < 8; w++) { S += rs[w]; Q += rq[w]; }
        g_psum[(b*8 + cx)*COUT + o] = S;
        g_psq [(b*8 + cx)*COUT + o] = Q;
    }
}

// ---------------- kernel: normalize + write output ----------------
__global__ void __launch_bounds__(256) k_out(const int* __restrict__ idx,
                                             const float* __restrict__ gamma,
                                             const float* __restrict__ beta,
                                             float* __restrict__ out) {
    __shared__ float sAm[64];
    __shared__ float sc, shf;
    const int tid = threadIdx.x;
    const int cx = blockIdx.x, o = blockIdx.y, b = blockIdx.z;
    if (tid < 64) sAm[tid] = g_adjmT[b*4096 + o*64 + tid];
    if (tid == 0) {
        float S = 0.f, Q = 0.f;
        #pragma unroll
        for (int i = 0; i < 16; i++) { S += g_psum[i*COUT + o]; Q += g_psq[i*COUT + o]; }
        const float invN = 1.0f / (float)NPIX;
        float mean = S * invN;
        float var  = Q * invN - mean * mean;
        float inv  = 1.0f / sqrtf(var + 1e-5f);
        float g = __ldg(gamma + o), be = __ldg(beta + o);
        sc  = g * inv;
        shf = be - mean * g * inv;
    }
    __syncthreads();
    const float4* xt4 = reinterpret_cast<const float4*>(g_xt + (size_t)(b*COUT + o) * HWD);
    const int4*   ip4 = reinterpret_cast<const int4*>(idx + b*HWD);
    float4* o4 = reinterpret_cast<float4*>(out + (size_t)(b*COUT + o) * HWD);
    int q0 = cx * 512 + tid;
    float lsc = sc, lsh = shf;
    #pragma unroll
    for (int it = 0; it < 2; it++) {
        int q = q0 + it*256;
        float4 v = __ldg(xt4 + q);
        int4 kk = __ldg(ip4 + q);
        float4 r;
        r.x = fmaxf(v.x + sAm[kk.x], 0.f) * lsc + lsh;
        r.y = fmaxf(v.y + sAm[kk.y], 0.f) * lsc + lsh;
        r.z = fmaxf(v.z + sAm[kk.z], 0.f) * lsc + lsh;
        r.w = fmaxf(v.w + sAm[kk.w], 0.f) * lsc + lsh;
        o4[q] = r;
    }
}

// ---------------- launch ----------------
extern "C" void kernel_launch(void* const* d_in, const int* in_sizes, int n_in,
                              void* d_out, int out_size) {
    const float* x     = (const float*)d_in[0];
    const int*   idx   = (const int*)  d_in[1];
    const float* Wft   = (const float*)d_in[2];
    const float* Wm    = (const float*)d_in[3];
    const float* gamma = (const float*)d_in[4];
    const float* beta  = (const float*)d_in[5];
    float* out = (float*)d_out;

    k_gemm<<<NGB + 1, 256>>>(x, Wft, Wm);
    k_sums<<<dim3(COUT + 1, BB, 2), 256>>>(idx);
    k_solve<<<BB, 64>>>();
    k_adj<<<BB*KK, 256>>>();
    k_stats<<<dim3(8, COUT, BB), 256>>>(idx);
    k_out<<<dim3(8, COUT, BB), 256>>>(idx, gamma, beta, out);
}

// round 16
// speedup vs baseline: 1.2313x; 1.2313x over previous
#include <cuda_runtime.h>
#include <cuda_bf16.h>
#include <cstdint>

#define BB 2
#define CIN 128
#define COUT 64
#define KK 64
#define HWD 16384          // 128*128
#define NPIX (BB*HWD)      // 32768
#define GPX 64             // pixels per gemm block
#define NGB (NPIX/GPX)     // 512 gemm blocks

// ---------------- scratch (device globals; no allocation) ----------------
__device__ float g_xt[BB*COUT*HWD];        // xt in [b][o][p] layout (8MB)
__device__ float g_sumsp[BB*KK*COUT*2];    // partial bin sums [b][k][o][z]
__device__ float g_cntp[BB*KK*2];          // partial counts   [b][k][z]
__device__ float g_L[COUT*COUT];           // Cholesky factor L (lower) of cov
__device__ float g_rd[COUT];               // 1/L[i][i]
__device__ float g_means[BB*KK*COUT];      // bin means [b][k][o]
__device__ float g_Z[BB*KK*COUT];          // z_k = L^-1 m_k, [b][k][o]
__device__ float g_adjmT[BB*KK*COUT];      // adj @ means, TRANSPOSED [b][o][i]
__device__ float g_psum[16*COUT];          // BN partial sums  [(b*8+cx)][o]
__device__ float g_psq[16*COUT];           // BN partial sumsq

// macro params named to avoid .x/.y/.z/.w member-token capture
#define FMA4(ACC_, XS_, WV_) { (ACC_).x += (XS_)*(WV_).x; (ACC_).y += (XS_)*(WV_).y; (ACC_).z += (XS_)*(WV_).z; (ACC_).w += (XS_)*(WV_).w; }

// ---------------- GEMM xt = x*Wft (block>0) + register-resident Cholesky (block 0) ----------------
__global__ void __launch_bounds__(256) k_gemm(const float* __restrict__ x,
                                              const float* __restrict__ Wft,
                                              const float* __restrict__ Wm) {
    __shared__ __align__(16) float sbuf[8192];   // gemm: W float4[2048]; chol: cov 64*65 then colbuf/dbuf
    const int tid = threadIdx.x;

    if (blockIdx.x == 0) {
        // ======== cov = Wm Wm^T, then Cholesky with matrix in registers ========
        for (int i = tid; i < 64*64; i += 256) sbuf[(i >> 6)*65 + (i & 63)] = Wm[i];
        __syncthreads();
        const int ti = tid & 15;
        const int tj = tid >> 4;
        float acc[4][4];
        #pragma unroll
        for (int p = 0; p < 4; p++)
            #pragma unroll
            for (int q = 0; q < 4; q++) acc[p][q] = 0.f;
        for (int c = 0; c < 64; c++) {
            float ai[4], bj[4];
            #pragma unroll
            for (int p = 0; p < 4; p++) ai[p] = sbuf[(ti*4 + p)*65 + c];
            #pragma unroll
            for (int q = 0; q < 4; q++) bj[q] = sbuf[(tj*4 + q)*65 + c];
            #pragma unroll
            for (int p = 0; p < 4; p++)
                #pragma unroll
                for (int q = 0; q < 4; q++) acc[p][q] += ai[p] * bj[q];
        }
        __syncthreads();
        #pragma unroll
        for (int p = 0; p < 4; p++)
            #pragma unroll
            for (int q = 0; q < 4; q++) sbuf[(ti*4 + p)*65 + tj*4 + q] = acc[p][q];
        __syncthreads();

        // 16 cells per thread in registers: row r, cols j0..j0+15
        const int r = tid & 63;
        const int part = tid >> 6;
        const int j0 = part*16;
        float creg[16];
        #pragma unroll
        for (int jj = 0; jj < 16; jj++) creg[jj] = sbuf[r*65 + j0 + jj];
        __syncthreads();   // cov reads done; sbuf[0..64] now colbuf/dbuf

        #pragma unroll
        for (int i = 0; i < 64; i++) {
            if (r == i && part == (i >> 4)) sbuf[64] = creg[i & 15];
            __syncthreads();
            if (part == (i >> 4) && r >= i) {
                float rpiv = rsqrtf(sbuf[64]);
                float Lv = creg[i & 15] * rpiv;
                creg[i & 15] = Lv;
                sbuf[r] = Lv;
                if (r == i) g_rd[i] = rpiv;
            }
            __syncthreads();
            if (r > i) {
                float f = sbuf[r];
                #pragma unroll
                for (int jj = 0; jj < 16; jj++) {
                    int j = j0 + jj;
                    if (j > i && j <= r) creg[jj] -= f * sbuf[j];
                }
            }
        }
        #pragma unroll
        for (int jj = 0; jj < 16; jj++) {
            int j = j0 + jj;
            g_L[r*64 + j] = (j <= r) ? creg[jj] : 0.f;
        }
        return;
    }

    // ======== GEMM: 64 px x 64 outs; 256 thr; thread tile 4px x 4out; register-pipelined LDG ========
    float4* sW4 = reinterpret_cast<float4*>(sbuf);          // [128c][16 f4]
    const int GP = (blockIdx.x - 1) * GPX;
    const int b  = GP >> 14;
    const int P0 = GP & (HWD - 1);
    const int quad = tid & 15;
    const int og   = tid >> 4;

    #pragma unroll
    for (int t = 0; t < 8; t++)
        sW4[tid + t*256] = __ldg(reinterpret_cast<const float4*>(Wft) + tid + t*256);
    __syncthreads();

    float4 a0 = make_float4(0.f,0.f,0.f,0.f), a1 = a0, a2 = a0, a3 = a0;

    const float* xb = x + (size_t)b * CIN * HWD + P0 + quad*4;
    const float4* sWp = sW4 + og;

    float4 L[4];
    #pragma unroll
    for (int i = 0; i < 4; i++)
        L[i] = *reinterpret_cast<const float4*>(xb + (size_t)i * HWD);

    for (int cb = 0; cb < CIN; cb += 4) {
        float4 M[4];
        if (cb + 4 < CIN) {
            #pragma unroll
            for (int i = 0; i < 4; i++)
                M[i] = *reinterpret_cast<const float4*>(xb + (size_t)(cb + 4 + i) * HWD);
        }
        #pragma unroll
        for (int i = 0; i < 4; i++) {
            float4 wv = sWp[(cb + i)*16];
            FMA4(a0, L[i].x, wv);
            FMA4(a1, L[i].y, wv);
            FMA4(a2, L[i].z, wv);
            FMA4(a3, L[i].w, wv);
        }
        #pragma unroll
        for (int i = 0; i < 4; i++) L[i] = M[i];
    }

    float* xtb = g_xt + (size_t)b * COUT * HWD + P0 + quad*4;
    const int ob = og*4;
    *reinterpret_cast<float4*>(xtb + (size_t)(ob+0) * HWD) = make_float4(a0.x, a1.x, a2.x, a3.x);
    *reinterpret_cast<float4*>(xtb + (size_t)(ob+1) * HWD) = make_float4(a0.y, a1.y, a2.y, a3.y);
    *reinterpret_cast<float4*>(xtb + (size_t)(ob+2) * HWD) = make_float4(a0.z, a1.z, a2.z, a3.z);
    *reinterpret_cast<float4*>(xtb + (size_t)(ob+3) * HWD) = make_float4(a0.w, a1.w, a2.w, a3.w);
}

// ---------------- kernel: per-bin partial sums + counts via shared atomics ----------------
__global__ void __launch_bounds__(256) k_sums(const int* __restrict__ idx) {
    __shared__ float sbm[64*33];
    const int tid = threadIdx.x;
    const int o = blockIdx.x, b = blockIdx.y, z = blockIdx.z;
    for (int i = tid; i < 64*33; i += 256) sbm[i] = 0.f;
    __syncthreads();
    const int col = tid & 31;
    const int4* ip4 = reinterpret_cast<const int4*>(idx + b*HWD);
    const int q0 = z*2048;
    if (o < COUT) {
        const float4* xt4 = reinterpret_cast<const float4*>(g_xt + (size_t)(b*COUT + o) * HWD);
        #pragma unroll
        for (int it = 0; it < 8; it++) {
            int q = q0 + it*256 + tid;
            float4 v = __ldg(xt4 + q);
            int4 kk = __ldg(ip4 + q);
            atomicAdd(&sbm[kk.x*33 + col], v.x);
            atomicAdd(&sbm[kk.y*33 + col], v.y);
            atomicAdd(&sbm[kk.z*33 + col], v.z);
            atomicAdd(&sbm[kk.w*33 + col], v.w);
        }
    } else {
        #pragma unroll
        for (int it = 0; it < 8; it++) {
            int q = q0 + it*256 + tid;
            int4 kk = __ldg(ip4 + q);
            atomicAdd(&sbm[kk.x*33 + col], 1.f);
            atomicAdd(&sbm[kk.y*33 + col], 1.f);
            atomicAdd(&sbm[kk.z*33 + col], 1.f);
            atomicAdd(&sbm[kk.w*33 + col], 1.f);
        }
    }
    __syncthreads();
    if (tid < 128) {
        int k = tid >> 1, h = tid & 1;
        float s = 0.f;
        const float* row = sbm + k*33 + h*16;
        #pragma unroll
        for (int m = 0; m < 16; m++) s += row[m];
        s += __shfl_xor_sync(0xffffffffu, s, 1);
        if (h == 0) {
            if (o < COUT) g_sumsp[((b*64 + k)*64 + o)*2 + z] = s;
            else          g_cntp[(b*64 + k)*2 + z] = s;
        }
    }
}

// ---------------- kernel: means + cooperative forward solve z = L^-1 m, one block per (b,k) ----------------
__global__ void __launch_bounds__(64) k_solve() {
    __shared__ float sL[64*65];     // padded: sL[r*65+c] -> conflict-free column reads
    __shared__ float srd[64];
    __shared__ float sz[64];
    const int tid = threadIdx.x;
    const int b = blockIdx.x >> 6;
    const int k = blockIdx.x & 63;

    for (int t = tid; t < 64*64; t += 64) sL[(t >> 6)*65 + (t & 63)] = g_L[t];
    srd[tid] = g_rd[tid];
    __syncthreads();

    float2 cp = *reinterpret_cast<const float2*>(g_cntp + (b*64 + k)*2);
    float cnt = cp.x + cp.y;
    float den = cnt + (cnt == 0.f ? 1.f : 0.f);
    float2 sp = *reinterpret_cast<const float2*>(g_sumsp + ((size_t)(b*64 + k)*64 + tid)*2);
    float m = __fdividef(sp.x + sp.y, den);
    g_means[(b*64 + k)*64 + tid] = m;

    float r = m;
    for (int i = 0; i < 64; i++) {
        if (tid == i) {
            float zv = r * srd[i];
            sz[i] = zv;
            g_Z[(size_t)(b*64 + k)*64 + i] = zv;
        }
        __syncthreads();
        if (tid > i) r -= sL[tid*65 + i] * sz[i];
    }
}

// ---------------- kernel: adjacency (||z_i - z_j||^2) + adj@means per (b,i) ----------------
__global__ void __launch_bounds__(256) k_adj() {
    __shared__ float sMe[64*65];
    __shared__ float sZ[64*65];
    __shared__ float adjrow[64];
    __shared__ float red[256];
    const int tid = threadIdx.x;
    const int b = blockIdx.x >> 6;
    const int i = blockIdx.x & 63;

    for (int t = tid; t < 64*64; t += 256) {
        int k = t >> 6, o = t & 63;
        sMe[k*65 + o] = __ldg(g_means + b*4096 + t);
        sZ[k*65 + o]  = __ldg(g_Z + b*4096 + t);
    }
    __syncthreads();

    const int j = tid & 63, s = tid >> 6;
    const float* zi = sZ + i*65;
    const float* zj = sZ + j*65;
    float q = 0.f;
    #pragma unroll
    for (int d = 0; d < 16; d++) {
        float df = zi[s*16 + d] - zj[s*16 + d];
        q += df * df;
    }
    red[tid] = q;
    __syncthreads();
    if (tid < 64) {
        float qt = red[tid] + red[64 + tid] + red[128 + tid] + red[192 + tid];
        float dist = (tid == i) ? 1e-6f : sqrtf(fmaxf(qt, 1e-12f));
        adjrow[tid] = expf(-dist);
    }
    __syncthreads();
    const int o = tid & 63;
    float part = 0.f;
    for (int jj = s*16; jj < s*16 + 16; jj++) part += adjrow[jj] * sMe[jj*65 + o];
    red[tid] = part;
    __syncthreads();
    if (tid < 64)
        g_adjmT[b*4096 + tid*64 + i] = red[tid] + red[64 + tid] + red[128 + tid] + red[192 + tid];
}

// ---------------- kernel: BN partial statistics ----------------
__global__ void __launch_bounds__(256) k_stats(const int* __restrict__ idx) {
    __shared__ float sAm[64];
    const int tid = threadIdx.x;
    const int cx = blockIdx.x, o = blockIdx.y, b = blockIdx.z;
    if (tid < 64) sAm[tid] = g_adjmT[b*4096 + o*64 + tid];
    __syncthreads();
    const float4* xt4 = reinterpret_cast<const float4*>(g_xt + (size_t)(b*COUT + o) * HWD);
    const int4*   ip4 = reinterpret_cast<const int4*>(idx + b*HWD);
    int q0 = cx * 512 + tid;
    float s = 0.f, sq = 0.f;
    #pragma unroll
    for (int it = 0; it < 2; it++) {
        int q = q0 + it*256;
        float4 v = __ldg(xt4 + q);
        int4 kk = __ldg(ip4 + q);
        float f0 = fmaxf(v.x + sAm[kk.x], 0.f);
        float f1 = fmaxf(v.y + sAm[kk.y], 0.f);
        float f2 = fmaxf(v.z + sAm[kk.z], 0.f);
        float f3 = fmaxf(v.w + sAm[kk.w], 0.f);
        s  += f0 + f1 + f2 + f3;
        sq += f0*f0 + f1*f1 + f2*f2 + f3*f3;
    }
    #pragma unroll
    for (int off = 16; off; off >>= 1) {
        s  += __shfl_down_sync(0xffffffffu, s, off);
        sq += __shfl_down_sync(0xffffffffu, sq, off);
    }
    __shared__ float rs[8], rq[8];
    if ((tid & 31) == 0) { rs[tid >> 5] = s; rq[tid >> 5] = sq; }
    __syncthreads();
    if (tid == 0) {
        float S = 0.f, Q = 0.f;
        #pragma unroll
        for (int w = 0; w < 8; w++) { S += rs[w]; Q += rq[w]; }
        g_psum[(b*8 + cx)*COUT + o] = S;
        g_psq [(b*8 + cx)*COUT + o] = Q;
    }
}

// ---------------- kernel: normalize + write output ----------------
__global__ void __launch_bounds__(256) k_out(const int* __restrict__ idx,
                                             const float* __restrict__ gamma,
                                             const float* __restrict__ beta,
                                             float* __restrict__ out) {
    __shared__ float sAm[64];
    __shared__ float sc, shf;
    const int tid = threadIdx.x;
    const int cx = blockIdx.x, o = blockIdx.y, b = blockIdx.z;
    if (tid < 64) sAm[tid] = g_adjmT[b*4096 + o*64 + tid];
    if (tid == 0) {
        float S = 0.f, Q = 0.f;
        #pragma unroll
        for (int i = 0; i < 16; i++) { S += g_psum[i*COUT + o]; Q += g_psq[i*COUT + o]; }
        const float invN = 1.0f / (float)NPIX;
        float mean = S * invN;
        float var  = Q * invN - mean * mean;
        float inv  = 1.0f / sqrtf(var + 1e-5f);
        float g = __ldg(gamma + o), be = __ldg(beta + o);
        sc  = g * inv;
        shf = be - mean * g * inv;
    }
    __syncthreads();
    const float4* xt4 = reinterpret_cast<const float4*>(g_xt + (size_t)(b*COUT + o) * HWD);
    const int4*   ip4 = reinterpret_cast<const int4*>(idx + b*HWD);
    float4* o4 = reinterpret_cast<float4*>(out + (size_t)(b*COUT + o) * HWD);
    int q0 = cx * 512 + tid;
    float lsc = sc, lsh = shf;
    #pragma unroll
    for (int it = 0; it < 2; it++) {
        int q = q0 + it*256;
        float4 v = __ldg(xt4 + q);
        int4 kk = __ldg(ip4 + q);
        float4 r;
        r.x = fmaxf(v.x + sAm[kk.x], 0.f) * lsc + lsh;
        r.y = fmaxf(v.y + sAm[kk.y], 0.f) * lsc + lsh;
        r.z = fmaxf(v.z + sAm[kk.z], 0.f) * lsc + lsh;
        r.w = fmaxf(v.w + sAm[kk.w], 0.f) * lsc + lsh;
        o4[q] = r;
    }
}

// ---------------- launch ----------------
extern "C" void kernel_launch(void* const* d_in, const int* in_sizes, int n_in,
                              void* d_out, int out_size) {
    const float* x     = (const float*)d_in[0];
    const int*   idx   = (const int*)  d_in[1];
    const float* Wft   = (const float*)d_in[2];
    const float* Wm    = (const float*)d_in[3];
    const float* gamma = (const float*)d_in[4];
    const float* beta  = (const float*)d_in[5];
    float* out = (float*)d_out;

    k_gemm<<<NGB + 1, 256>>>(x, Wft, Wm);
    k_sums<<<dim3(COUT + 1, BB, 2), 256>>>(idx);
    k_solve<<<BB*KK, 64>>>();
    k_adj<<<BB*KK, 256>>>();
    k_stats<<<dim3(8, COUT, BB), 256>>>(idx);
    k_out<<<dim3(8, COUT, BB), 256>>>(idx, gamma, beta, out);
}